// round 2
// baseline (speedup 1.0000x reference)
#include <cuda_runtime.h>
#include <cuda_pipeline.h>
#include <math.h>

#define N_TOK  16384
#define DIM    4096
#define NEXP   64
#define TOPK   8
#define KC     128
#define TPB    128               // tokens per block
#define NCHUNK (DIM / KC)        // 32
#define NBLK   (N_TOK / TPB)     // 128

// ---- dynamic smem layout (float offsets) ----
#define XS0 0
#define XS1 16384
#define WS0 32768
#define WS1 (32768 + 8448)
#define SMEM_FLOATS (32768 + 2 * 8448)     // 49664 floats = 198656 B
#define LS  0                               // logits [128][66], aliases XS0
#define BIAS_S (128 * 66)                   // 64 floats, still inside XS0 region

__device__ float g_partial[NBLK * NEXP];    // deterministic per-block expert sums

__device__ __forceinline__ unsigned long long pack2(float v) {
    unsigned long long r;
    asm("mov.b64 %0, {%1, %2};" : "=l"(r) : "f"(v), "f"(v));
    return r;
}
__device__ __forceinline__ unsigned long long fma2(unsigned long long a,
                                                   unsigned long long b,
                                                   unsigned long long c) {
    unsigned long long d;
    asm("fma.rn.f32x2 %0, %1, %2, %3;" : "=l"(d) : "l"(a), "l"(b), "l"(c));
    return d;
}
__device__ __forceinline__ unsigned long long add2(unsigned long long a,
                                                   unsigned long long b) {
    unsigned long long d;
    asm("add.rn.f32x2 %0, %1, %2;" : "=l"(d) : "l"(a), "l"(b));
    return d;
}

// Stage one K-chunk of x (128 tok x 128 k, XOR-swizzled) and W (128 k x 64 e, pad 66)
__device__ __forceinline__ void load_chunk(float* sm, int xbuf, int wbuf,
                                           const float* __restrict__ x,
                                           const float* __restrict__ W,
                                           int tok0, int kc, int tid) {
    const int lane = tid & 31;
    const int warp = tid >> 5;

#pragma unroll 8
    for (int rr = 0; rr < 32; rr++) {
        const int r = warp + 4 * rr;
        const float* src = x + (size_t)(tok0 + r) * DIM + kc + lane;
        float* dstrow = sm + xbuf + r * 128;
        const int sw = r & 31;
#pragma unroll
        for (int j = 0; j < 4; j++) {
            const int k = lane + 32 * j;
            __pipeline_memcpy_async(dstrow + (k ^ sw), src + 32 * j, 4);
        }
    }
#pragma unroll 4
    for (int ee = 0; ee < 16; ee++) {
        const int e = warp + 4 * ee;
        const float* src = W + (size_t)e * DIM + kc + lane;
#pragma unroll
        for (int j = 0; j < 4; j++) {
            const int k = lane + 32 * j;
            __pipeline_memcpy_async(sm + wbuf + k * 66 + e, src + 32 * j, 4);
        }
    }
}

// Accumulate one K-chunk into a FRESH accumulator (reduces rounding error).
__device__ __forceinline__ void compute_chunk(const float* sm, int xbuf, int wbuf,
                                              unsigned long long accC[4][8],
                                              int lane, int warp) {
#pragma unroll
    for (int t = 0; t < 4; t++)
#pragma unroll
        for (int p = 0; p < 8; p++) accC[t][p] = 0ull;

#pragma unroll 4
    for (int k = 0; k < KC; k++) {
        unsigned long long xp[4];
#pragma unroll
        for (int t = 0; t < 4; t++) {
            const float xv = sm[xbuf + (lane + 32 * t) * 128 + (k ^ lane)];
            xp[t] = pack2(xv);
        }
        const float* wrow = sm + wbuf + k * 66 + warp * 16;
#pragma unroll
        for (int p = 0; p < 8; p++) {
            const unsigned long long wp =
                *reinterpret_cast<const unsigned long long*>(wrow + 2 * p);
#pragma unroll
            for (int t = 0; t < 4; t++)
                accC[t][p] = fma2(xp[t], wp, accC[t][p]);
        }
    }
}

extern "C" __global__ void __launch_bounds__(128, 1)
moe_main(const float* __restrict__ x, const float* __restrict__ W,
         const float* __restrict__ bias, float* __restrict__ out) {
    extern __shared__ float sm[];
    const int tid  = threadIdx.x;
    const int lane = tid & 31;
    const int warp = tid >> 5;
    const int tok0 = blockIdx.x * TPB;

    unsigned long long accM[4][8];   // master
    unsigned long long accC[4][8];   // per-chunk (reset each chunk)
#pragma unroll
    for (int t = 0; t < 4; t++)
#pragma unroll
        for (int p = 0; p < 8; p++) accM[t][p] = 0ull;

    // --- software-pipelined GEMM over K chunks ---
    load_chunk(sm, XS0, WS0, x, W, tok0, 0, tid);
    __pipeline_commit();
    __pipeline_wait_prior(0);
    __syncthreads();

    for (int c = 0; c < NCHUNK; c++) {
        const int xb = (c & 1) ? XS1 : XS0;
        const int wb = (c & 1) ? WS1 : WS0;
        if (c + 1 < NCHUNK) {
            load_chunk(sm, (c & 1) ? XS0 : XS1, (c & 1) ? WS0 : WS1,
                       x, W, tok0, (c + 1) * KC, tid);
            __pipeline_commit();
        }
        compute_chunk(sm, xb, wb, accC, lane, warp);
#pragma unroll
        for (int t = 0; t < 4; t++)
#pragma unroll
            for (int p = 0; p < 8; p++) accM[t][p] = add2(accM[t][p], accC[t][p]);
        if (c + 1 < NCHUNK) __pipeline_wait_prior(0);
        __syncthreads();
    }

    // --- spill logits to smem (alias over XS0; last compute used XS1) ---
#pragma unroll
    for (int t = 0; t < 4; t++) {
        const int tok = lane + 32 * t;
#pragma unroll
        for (int p = 0; p < 8; p++) {
            float lo, hi;
            asm("mov.b64 {%0, %1}, %2;" : "=f"(lo), "=f"(hi) : "l"(accM[t][p]));
            sm[LS + tok * 66 + warp * 16 + 2 * p]     = lo;
            sm[LS + tok * 66 + warp * 16 + 2 * p + 1] = hi;
        }
    }
    if (tid < NEXP) sm[BIAS_S + tid] = bias[tid];
    __syncthreads();

    // --- phase 2: softmax + top-8 per token (thread == token) ---
    const int tok = tid;
    float lv[NEXP];
    float mx = -INFINITY;
#pragma unroll
    for (int e = 0; e < NEXP; e++) {
        const float v = sm[LS + tok * 66 + e] + sm[BIAS_S + e];
        lv[e] = v;
        mx = fmaxf(mx, v);
    }
    float s = 0.0f;
#pragma unroll
    for (int e = 0; e < NEXP; e++) {
        lv[e] = expf(lv[e] - mx);
        s += lv[e];
    }
    const float inv = 1.0f / s;
#pragma unroll
    for (int e = 0; e < NEXP; e++) {
        lv[e] *= inv;
        sm[LS + tok * 66 + e] = lv[e];   // normalized probs for column sums
    }
    __syncthreads();

    // deterministic per-expert partial sums (no atomics)
    if (tid < NEXP) {
        float cs = 0.0f;
        for (int t = 0; t < TPB; t++) cs += sm[LS + t * 66 + tid];
        g_partial[blockIdx.x * NEXP + tid] = cs;
    }

    // top-8 on register copy; tie-break = lowest index first (matches lax.top_k)
    const int gt = tok0 + tok;
    float prevV = INFINITY;
    int   prevE = -1;
    float* o_ids = out;
    float* o_p   = out + (size_t)N_TOK * 8;
#pragma unroll
    for (int r = 0; r < TOPK; r++) {
        float bv = -INFINITY;
        int   be = 0;
#pragma unroll
        for (int e = 0; e < NEXP; e++) {
            const float v = lv[e];
            const bool elig = (v < prevV) || (v == prevV && e > prevE);
            if (elig && v > bv) { bv = v; be = e; }
        }
        o_ids[(size_t)gt * 8 + r] = (float)be;
        o_p[(size_t)gt * 8 + r]   = bv;
        prevV = bv; prevE = be;
    }

    // shared experts: ids {0,1}, probs {0.5,0.5}
    out[(size_t)N_TOK * 16 + gt * 2 + 0] = 0.0f;
    out[(size_t)N_TOK * 16 + gt * 2 + 1] = 1.0f;
    out[(size_t)N_TOK * 18 + gt * 2 + 0] = 0.5f;
    out[(size_t)N_TOK * 18 + gt * 2 + 1] = 0.5f;
}

__global__ void aux_kernel(float* __restrict__ out) {
    __shared__ float sq[NEXP];
    const int e = threadIdx.x;
    float s = 0.0f;
    for (int b = 0; b < NBLK; b++) s += g_partial[b * NEXP + e];
    const float m = s / (float)N_TOK;
    sq[e] = m * m;
    __syncthreads();
    if (e == 0) {
        float t = 0.0f;
        for (int i = 0; i < NEXP; i++) t += sq[i];
        out[(size_t)N_TOK * 20] = 0.01f * (t / (float)NEXP);
    }
}

extern "C" void kernel_launch(void* const* d_in, const int* in_sizes, int n_in,
                              void* d_out, int out_size) {
    const float* x    = (const float*)d_in[0];
    const float* W    = (const float*)d_in[1];
    const float* bias = (const float*)d_in[2];
    float* out = (float*)d_out;

    const size_t smem = (size_t)SMEM_FLOATS * sizeof(float);   // 198656 B
    cudaFuncSetAttribute(moe_main, cudaFuncAttributeMaxDynamicSharedMemorySize,
                         (int)smem);
    moe_main<<<NBLK, 128, smem>>>(x, W, bias, out);
    aux_kernel<<<1, NEXP>>>(out);
}

// round 5
// speedup vs baseline: 1.5116x; 1.5116x over previous
#include <cuda_runtime.h>
#include <cuda_pipeline.h>
#include <math.h>

#define N_TOK  16384
#define DIM    4096
#define NEXP   64
#define TOPK   8
#define TPB    128               // tokens per CTA
#define KC     64                // k per chunk
#define KSTEPS (KC / 8)          // 8
#define NCHUNK (DIM / KC)        // 64
#define NBLK   (N_TOK / TPB)     // 128
#define PAD    68                // row stride in floats (64 + 4)

typedef unsigned int u32;

// ---- global scratch ----
__device__ __align__(16) float g_Whi[NEXP * DIM];   // tf32-rounded hi part
__device__ __align__(16) float g_Wlo[NEXP * DIM];   // tf32-rounded residual
__device__ float g_partial[NBLK * NEXP];

// ---- smem byte offsets ----
#define XS(b)  ((b) * 34816)                    // 128 x 68 floats
#define WH(b)  (69632 + (b) * 34816)            // 64 x 68 floats (hi)
#define WL(b)  (69632 + (b) * 34816 + 17408)    // 64 x 68 floats (lo)
#define SMEM_BYTES 139264
#define PROBS  0                                 // phase-2 alias: float[128][66]
#define BIAS_S 33792                             // float[64]

static __device__ __forceinline__ u32 tf32_hi(float v) {
    u32 r;
    asm("cvt.rna.tf32.f32 %0, %1;" : "=r"(r) : "f"(v));
    return r;
}
// D = A*B + C (accumulate in place)
static __device__ __forceinline__ void mma_tf32(float* c, u32 a0, u32 a1, u32 a2,
                                                u32 a3, u32 b0, u32 b1) {
    asm volatile(
        "mma.sync.aligned.m16n8k8.row.col.f32.tf32.tf32.f32 "
        "{%0,%1,%2,%3}, {%4,%5,%6,%7}, {%8,%9}, {%0,%1,%2,%3};"
        : "+f"(c[0]), "+f"(c[1]), "+f"(c[2]), "+f"(c[3])
        : "r"(a0), "r"(a1), "r"(a2), "r"(a3), "r"(b0), "r"(b1));
}
// D = A*B + 0  (fresh accumulator, no explicit zeroing)
static __device__ __forceinline__ void mma_tf32_z(float* d, u32 a0, u32 a1, u32 a2,
                                                  u32 a3, u32 b0, u32 b1) {
    asm volatile(
        "mma.sync.aligned.m16n8k8.row.col.f32.tf32.tf32.f32 "
        "{%0,%1,%2,%3}, {%4,%5,%6,%7}, {%8,%9}, {%10,%10,%10,%10};"
        : "=f"(d[0]), "=f"(d[1]), "=f"(d[2]), "=f"(d[3])
        : "r"(a0), "r"(a1), "r"(a2), "r"(a3), "r"(b0), "r"(b1), "f"(0.0f));
}

// ---- W split pre-kernel: fp32 -> (hi, lo) tf32 patterns ----
extern "C" __global__ void wconv_kernel(const float* __restrict__ W) {
    const int i = blockIdx.x * blockDim.x + threadIdx.x;   // over 262144 floats
    const float w = W[i];
    const u32 h = tf32_hi(w);
    const float lo = w - __uint_as_float(h);
    g_Whi[i] = __uint_as_float(h);
    g_Wlo[i] = __uint_as_float(tf32_hi(lo));
}

extern "C" __global__ void __launch_bounds__(128, 1)
moe_main(const float* __restrict__ x, const float* __restrict__ bias,
         float* __restrict__ out) {
    extern __shared__ char sm[];
    const int tid  = threadIdx.x;
    const int wid  = tid >> 5;
    const int lane = tid & 31;
    const int g    = lane >> 2;          // groupID 0..7
    const int t    = lane & 3;           // threadID in group 0..3
    const int tok0 = blockIdx.x * TPB;
    const int warpM = wid * 32;

    // ---- cp.async stagers ----
    auto issue_chunk = [&](int c) {
        const int b  = c & 1;
        const int kc = c * KC;
#pragma unroll
        for (int i = 0; i < 16; i++) {
            const int flat = tid + (i << 7);
            const int row = flat >> 4;
            const int j   = flat & 15;
            __pipeline_memcpy_async(sm + XS(b) + row * (PAD * 4) + j * 16,
                                    x + (size_t)(tok0 + row) * DIM + kc + 4 * j, 16);
        }
#pragma unroll
        for (int i = 0; i < 8; i++) {
            const int flat = tid + (i << 7);
            const int n = flat >> 4;
            const int j = flat & 15;
            __pipeline_memcpy_async(sm + WH(b) + n * (PAD * 4) + j * 16,
                                    g_Whi + (size_t)n * DIM + kc + 4 * j, 16);
            __pipeline_memcpy_async(sm + WL(b) + n * (PAD * 4) + j * 16,
                                    g_Wlo + (size_t)n * DIM + kc + 4 * j, 16);
        }
    };

    // ---- accumulators ----
    float accM[2][8][4];     // master fp32 (RN adds, flip-safe)
    float hh[2][8][4];       // per-chunk hi*hi MMA accumulator (reset each chunk)
    float accx[2][8][4];     // cross terms hi*lo + lo*hi (chained; magnitude ~2^-11)
#pragma unroll
    for (int m = 0; m < 2; m++)
#pragma unroll
        for (int j = 0; j < 8; j++)
#pragma unroll
            for (int q = 0; q < 4; q++) { accM[m][j][q] = 0.f; accx[m][j][q] = 0.f; }

    issue_chunk(0);
    __pipeline_commit();

#pragma unroll 1
    for (int c = 0; c < NCHUNK; c++) {
        const int b = c & 1;
        if (c + 1 < NCHUNK) issue_chunk(c + 1);
        __pipeline_commit();
        __pipeline_wait_prior((c + 1 < NCHUNK) ? 1 : 0);
        __syncthreads();

        const float* xs  = reinterpret_cast<const float*>(sm + XS(b));
        const float* whp = reinterpret_cast<const float*>(sm + WH(b));
        const float* wlp = reinterpret_cast<const float*>(sm + WL(b));

#pragma unroll
        for (int ks = 0; ks < KSTEPS; ks++) {
            const int k0 = ks * 8;
            u32 ah[8], al[8];
#pragma unroll
            for (int m = 0; m < 2; m++) {
                const int r0 = warpM + 16 * m + g;
                const float a0 = xs[r0 * PAD + k0 + t];
                const float a1 = xs[(r0 + 8) * PAD + k0 + t];
                const float a2 = xs[r0 * PAD + k0 + t + 4];
                const float a3 = xs[(r0 + 8) * PAD + k0 + t + 4];
                const u32 h0 = tf32_hi(a0), h1 = tf32_hi(a1);
                const u32 h2 = tf32_hi(a2), h3 = tf32_hi(a3);
                ah[4 * m + 0] = h0; ah[4 * m + 1] = h1;
                ah[4 * m + 2] = h2; ah[4 * m + 3] = h3;
                al[4 * m + 0] = tf32_hi(a0 - __uint_as_float(h0));
                al[4 * m + 1] = tf32_hi(a1 - __uint_as_float(h1));
                al[4 * m + 2] = tf32_hi(a2 - __uint_as_float(h2));
                al[4 * m + 3] = tf32_hi(a3 - __uint_as_float(h3));
            }
#pragma unroll
            for (int j = 0; j < 8; j++) {
                const int base = (8 * j + g) * PAD + k0 + t;
                const u32 bh0 = __float_as_uint(whp[base]);
                const u32 bh1 = __float_as_uint(whp[base + 4]);
                const u32 bl0 = __float_as_uint(wlp[base]);
                const u32 bl1 = __float_as_uint(wlp[base + 4]);
#pragma unroll
                for (int m = 0; m < 2; m++) {
                    if (ks == 0)
                        mma_tf32_z(hh[m][j], ah[4*m], ah[4*m+1], ah[4*m+2], ah[4*m+3], bh0, bh1);
                    else
                        mma_tf32(hh[m][j], ah[4*m], ah[4*m+1], ah[4*m+2], ah[4*m+3], bh0, bh1);
                    mma_tf32(accx[m][j], ah[4*m], ah[4*m+1], ah[4*m+2], ah[4*m+3], bl0, bl1);
                    mma_tf32(accx[m][j], al[4*m], al[4*m+1], al[4*m+2], al[4*m+3], bh0, bh1);
                }
            }
        }
        // fold chunk result into master with RN adds (breaks error chaining)
#pragma unroll
        for (int m = 0; m < 2; m++)
#pragma unroll
            for (int j = 0; j < 8; j++)
#pragma unroll
                for (int q = 0; q < 4; q++) accM[m][j][q] += hh[m][j][q];
        __syncthreads();
    }

    // ---- epilogue: combine accumulators, write logits to smem ----
    float* ps = reinterpret_cast<float*>(sm + PROBS);   // [128][66]
#pragma unroll
    for (int m = 0; m < 2; m++) {
        const int r0 = warpM + 16 * m + g;
#pragma unroll
        for (int j = 0; j < 8; j++) {
            const int col = 8 * j + 2 * t;
            const float f0 = accM[m][j][0] + accx[m][j][0];
            const float f1 = accM[m][j][1] + accx[m][j][1];
            const float f2 = accM[m][j][2] + accx[m][j][2];
            const float f3 = accM[m][j][3] + accx[m][j][3];
            *reinterpret_cast<float2*>(ps + r0 * 66 + col)       = make_float2(f0, f1);
            *reinterpret_cast<float2*>(ps + (r0 + 8) * 66 + col) = make_float2(f2, f3);
        }
    }
    if (tid < NEXP) reinterpret_cast<float*>(sm + BIAS_S)[tid] = bias[tid];
    __syncthreads();

    // ---- phase 2: softmax + top-8 (thread == token) ----
    const int tok = tid;
    const float* bs = reinterpret_cast<const float*>(sm + BIAS_S);
    float lv[NEXP];
    float mx = -INFINITY;
#pragma unroll
    for (int e = 0; e < NEXP; e++) {
        const float v = ps[tok * 66 + e] + bs[e];
        lv[e] = v;
        mx = fmaxf(mx, v);
    }
    float ssum = 0.0f;
#pragma unroll
    for (int e = 0; e < NEXP; e++) {
        lv[e] = expf(lv[e] - mx);
        ssum += lv[e];
    }
    const float inv = 1.0f / ssum;
    __syncthreads();   // logits no longer needed; overwrite with probs
#pragma unroll
    for (int e = 0; e < NEXP; e++) {
        lv[e] *= inv;
        ps[tok * 66 + e] = lv[e];
    }
    __syncthreads();

    if (tid < NEXP) {
        float cs = 0.0f;
        for (int tt = 0; tt < TPB; tt++) cs += ps[tt * 66 + tid];
        g_partial[blockIdx.x * NEXP + tid] = cs;
    }

    const int gt = tok0 + tok;
    float prevV = INFINITY;
    int   prevE = -1;
    float* o_ids = out;
    float* o_p   = out + (size_t)N_TOK * 8;
#pragma unroll
    for (int r = 0; r < TOPK; r++) {
        float bv = -INFINITY;
        int   be = 0;
#pragma unroll
        for (int e = 0; e < NEXP; e++) {
            const float v = lv[e];
            const bool elig = (v < prevV) || (v == prevV && e > prevE);
            if (elig && v > bv) { bv = v; be = e; }
        }
        o_ids[(size_t)gt * 8 + r] = (float)be;
        o_p[(size_t)gt * 8 + r]   = bv;
        prevV = bv; prevE = be;
    }

    out[(size_t)N_TOK * 16 + gt * 2 + 0] = 0.0f;
    out[(size_t)N_TOK * 16 + gt * 2 + 1] = 1.0f;
    out[(size_t)N_TOK * 18 + gt * 2 + 0] = 0.5f;
    out[(size_t)N_TOK * 18 + gt * 2 + 1] = 0.5f;
}

__global__ void aux_kernel(float* __restrict__ out) {
    __shared__ float sq[NEXP];
    const int e = threadIdx.x;
    float s = 0.0f;
    for (int b = 0; b < NBLK; b++) s += g_partial[b * NEXP + e];
    const float m = s / (float)N_TOK;
    sq[e] = m * m;
    __syncthreads();
    if (e == 0) {
        float tot = 0.0f;
        for (int i = 0; i < NEXP; i++) tot += sq[i];
        out[(size_t)N_TOK * 20] = 0.01f * (tot / (float)NEXP);
    }
}

extern "C" void kernel_launch(void* const* d_in, const int* in_sizes, int n_in,
                              void* d_out, int out_size) {
    const float* x    = (const float*)d_in[0];
    const float* W    = (const float*)d_in[1];
    const float* bias = (const float*)d_in[2];
    float* out = (float*)d_out;

    cudaFuncSetAttribute(moe_main, cudaFuncAttributeMaxDynamicSharedMemorySize,
                         SMEM_BYTES);
    wconv_kernel<<<NEXP * DIM / 256, 256>>>(W);
    moe_main<<<NBLK, 128, SMEM_BYTES>>>(x, bias, out);
    aux_kernel<<<1, NEXP>>>(out);
}

// round 6
// speedup vs baseline: 1.6177x; 1.0703x over previous
#include <cuda_runtime.h>
#include <cuda_pipeline.h>
#include <math.h>

#define N_TOK  16384
#define DIM    4096
#define NEXP   64
#define TOPK   8
#define TPB    128               // tokens per CTA
#define NTHR   256               // 8 warps
#define KC     64                // k per chunk
#define KSTEPS (KC / 8)          // 8
#define NCHUNK (DIM / KC)        // 64
#define NBLK   (N_TOK / TPB)     // 128
#define PAD    68                // x row stride in floats

typedef unsigned int u32;

// ---- global scratch ----
// Packed W fragment quads: [chunk][ks][n][t] -> {hi(k+t), hi(k+t+4), lo(k+t), lo(k+t+4)}
__device__ __align__(16) float4 g_Wq[NCHUNK * KSTEPS * NEXP * 4];
__device__ float g_partial[NBLK * NEXP];

// ---- smem byte offsets ----
#define XS(b)  ((b) * 34816)                    // 128 x 68 floats
#define WQ(b)  (69632 + (b) * 32768)            // 2048 float4
#define SMEM_BYTES 135168
#define PROBS  0                                 // phase-2 alias: float[128][66]
#define BIAS_S 33792                             // float[64]

static __device__ __forceinline__ u32 tf32_hi(float v) {
    u32 r;
    asm("cvt.rna.tf32.f32 %0, %1;" : "=r"(r) : "f"(v));
    return r;
}
static __device__ __forceinline__ void mma_tf32(float* c, u32 a0, u32 a1, u32 a2,
                                                u32 a3, u32 b0, u32 b1) {
    asm volatile(
        "mma.sync.aligned.m16n8k8.row.col.f32.tf32.tf32.f32 "
        "{%0,%1,%2,%3}, {%4,%5,%6,%7}, {%8,%9}, {%0,%1,%2,%3};"
        : "+f"(c[0]), "+f"(c[1]), "+f"(c[2]), "+f"(c[3])
        : "r"(a0), "r"(a1), "r"(a2), "r"(a3), "r"(b0), "r"(b1));
}
static __device__ __forceinline__ void mma_tf32_z(float* d, u32 a0, u32 a1, u32 a2,
                                                  u32 a3, u32 b0, u32 b1) {
    asm volatile(
        "mma.sync.aligned.m16n8k8.row.col.f32.tf32.tf32.f32 "
        "{%0,%1,%2,%3}, {%4,%5,%6,%7}, {%8,%9}, {%10,%10,%10,%10};"
        : "=f"(d[0]), "=f"(d[1]), "=f"(d[2]), "=f"(d[3])
        : "r"(a0), "r"(a1), "r"(a2), "r"(a3), "r"(b0), "r"(b1), "f"(0.0f));
}

// ---- W pre-pack: fp32 -> fragment quads (hi/lo tf32 patterns) ----
extern "C" __global__ void wconv_kernel(const float* __restrict__ W) {
    const int idx = blockIdx.x * blockDim.x + threadIdx.x;   // 131072 quads
    const int t  = idx & 3;
    const int n  = (idx >> 2) & 63;
    const int ks = (idx >> 8) & 7;
    const int c  = idx >> 11;
    const int k  = c * KC + ks * 8 + t;
    const float w0 = W[(size_t)n * DIM + k];
    const float w1 = W[(size_t)n * DIM + k + 4];
    const u32 h0 = tf32_hi(w0);
    const u32 h1 = tf32_hi(w1);
    float4 q;
    q.x = __uint_as_float(h0);
    q.y = __uint_as_float(h1);
    q.z = __uint_as_float(tf32_hi(w0 - __uint_as_float(h0)));
    q.w = __uint_as_float(tf32_hi(w1 - __uint_as_float(h1)));
    g_Wq[idx] = q;
}

extern "C" __global__ void __launch_bounds__(NTHR, 1)
moe_main(const float* __restrict__ x, const float* __restrict__ bias,
         float* __restrict__ out) {
    extern __shared__ char sm[];
    const int tid  = threadIdx.x;
    const int wid  = tid >> 5;
    const int lane = tid & 31;
    const int g    = lane >> 2;          // groupID 0..7
    const int t    = lane & 3;           // threadID in group 0..3
    const int tok0 = blockIdx.x * TPB;
    const int warpM = wid * 16;          // each warp owns one m16 tile

    // ---- cp.async stagers (256 threads) ----
    auto issue_chunk = [&](int c) {
        const int b  = c & 1;
        const int kc = c * KC;
        // x: 2048 float4 -> 8 per thread
#pragma unroll
        for (int i = 0; i < 8; i++) {
            const int flat = tid + (i << 8);
            const int row = flat >> 4;
            const int j   = flat & 15;
            __pipeline_memcpy_async(sm + XS(b) + row * (PAD * 4) + j * 16,
                                    x + (size_t)(tok0 + row) * DIM + kc + 4 * j, 16);
        }
        // W quads: 2048 float4 contiguous -> 8 per thread
        const float4* src = g_Wq + (size_t)c * (KSTEPS * NEXP * 4);
#pragma unroll
        for (int i = 0; i < 8; i++) {
            const int flat = tid + (i << 8);
            __pipeline_memcpy_async(sm + WQ(b) + flat * 16, src + flat, 16);
        }
    };

    // ---- accumulators: [ntile j][4] ----
    float accM[8][4];    // master fp32 (RN adds)
    float hh[8][4];      // per-chunk hi*hi (reset each chunk via mma_tf32_z)
    float accx[8][4];    // cross terms (chained; magnitude ~2^-11)
#pragma unroll
    for (int j = 0; j < 8; j++)
#pragma unroll
        for (int q = 0; q < 4; q++) { accM[j][q] = 0.f; accx[j][q] = 0.f; }

    issue_chunk(0);
    __pipeline_commit();

#pragma unroll 1
    for (int c = 0; c < NCHUNK; c++) {
        const int b = c & 1;
        if (c + 1 < NCHUNK) issue_chunk(c + 1);
        __pipeline_commit();
        __pipeline_wait_prior((c + 1 < NCHUNK) ? 1 : 0);
        __syncthreads();

        const float* xs = reinterpret_cast<const float*>(sm + XS(b));
        const float4* wq = reinterpret_cast<const float4*>(sm + WQ(b));

#pragma unroll
        for (int ks = 0; ks < KSTEPS; ks++) {
            const int k0 = ks * 8;
            // A fragment (one m16 tile), split tf32 hi/lo
            const int r0 = warpM + g;
            const float a0 = xs[r0 * PAD + k0 + t];
            const float a1 = xs[(r0 + 8) * PAD + k0 + t];
            const float a2 = xs[r0 * PAD + k0 + t + 4];
            const float a3 = xs[(r0 + 8) * PAD + k0 + t + 4];
            const u32 h0 = tf32_hi(a0), h1 = tf32_hi(a1);
            const u32 h2 = tf32_hi(a2), h3 = tf32_hi(a3);
            const u32 l0 = tf32_hi(a0 - __uint_as_float(h0));
            const u32 l1 = tf32_hi(a1 - __uint_as_float(h1));
            const u32 l2 = tf32_hi(a2 - __uint_as_float(h2));
            const u32 l3 = tf32_hi(a3 - __uint_as_float(h3));

            const float4* wrow = wq + (ks * NEXP + g) * 4 + t;
#pragma unroll
            for (int j = 0; j < 8; j++) {
                const float4 q = wrow[j * 32];   // n = 8j+g
                const u32 bh0 = __float_as_uint(q.x);
                const u32 bh1 = __float_as_uint(q.y);
                const u32 bl0 = __float_as_uint(q.z);
                const u32 bl1 = __float_as_uint(q.w);
                if (ks == 0) mma_tf32_z(hh[j], h0, h1, h2, h3, bh0, bh1);
                else         mma_tf32(hh[j], h0, h1, h2, h3, bh0, bh1);
                mma_tf32(accx[j], h0, h1, h2, h3, bl0, bl1);
                mma_tf32(accx[j], l0, l1, l2, l3, bh0, bh1);
            }
        }
        // fold chunk hi*hi into master with RN adds (breaks truncation chaining)
#pragma unroll
        for (int j = 0; j < 8; j++)
#pragma unroll
            for (int q = 0; q < 4; q++) accM[j][q] += hh[j][q];
        __syncthreads();
    }

    // ---- epilogue: combine, write logits to smem ----
    float* ps = reinterpret_cast<float*>(sm + PROBS);   // [128][66]
    {
        const int r0 = warpM + g;
#pragma unroll
        for (int j = 0; j < 8; j++) {
            const int col = 8 * j + 2 * t;
            const float f0 = accM[j][0] + accx[j][0];
            const float f1 = accM[j][1] + accx[j][1];
            const float f2 = accM[j][2] + accx[j][2];
            const float f3 = accM[j][3] + accx[j][3];
            *reinterpret_cast<float2*>(ps + r0 * 66 + col)       = make_float2(f0, f1);
            *reinterpret_cast<float2*>(ps + (r0 + 8) * 66 + col) = make_float2(f2, f3);
        }
    }
    if (tid < NEXP) reinterpret_cast<float*>(sm + BIAS_S)[tid] = bias[tid];
    __syncthreads();

    // ---- phase 2: softmax + top-8 (threads 0..127, thread == token) ----
    const int tok = tid;
    float lv[NEXP];
    if (tok < TPB) {
        const float* bs = reinterpret_cast<const float*>(sm + BIAS_S);
        float mx = -INFINITY;
#pragma unroll
        for (int e = 0; e < NEXP; e++) {
            const float v = ps[tok * 66 + e] + bs[e];
            lv[e] = v;
            mx = fmaxf(mx, v);
        }
        float ssum = 0.0f;
#pragma unroll
        for (int e = 0; e < NEXP; e++) {
            lv[e] = expf(lv[e] - mx);
            ssum += lv[e];
        }
        const float inv = 1.0f / ssum;
#pragma unroll
        for (int e = 0; e < NEXP; e++) lv[e] *= inv;
    }
    __syncthreads();   // logits read done; now overwrite with probs
    if (tok < TPB) {
#pragma unroll
        for (int e = 0; e < NEXP; e++) ps[tok * 66 + e] = lv[e];
    }
    __syncthreads();

    if (tid < NEXP) {
        float cs = 0.0f;
        for (int tt = 0; tt < TPB; tt++) cs += ps[tt * 66 + tid];
        g_partial[blockIdx.x * NEXP + tid] = cs;
    }

    if (tok < TPB) {
        const int gt = tok0 + tok;
        float prevV = INFINITY;
        int   prevE = -1;
        float* o_ids = out;
        float* o_p   = out + (size_t)N_TOK * 8;
#pragma unroll
        for (int r = 0; r < TOPK; r++) {
            float bv = -INFINITY;
            int   be = 0;
#pragma unroll
            for (int e = 0; e < NEXP; e++) {
                const float v = lv[e];
                const bool elig = (v < prevV) || (v == prevV && e > prevE);
                if (elig && v > bv) { bv = v; be = e; }
            }
            o_ids[(size_t)gt * 8 + r] = (float)be;
            o_p[(size_t)gt * 8 + r]   = bv;
            prevV = bv; prevE = be;
        }
        out[(size_t)N_TOK * 16 + gt * 2 + 0] = 0.0f;
        out[(size_t)N_TOK * 16 + gt * 2 + 1] = 1.0f;
        out[(size_t)N_TOK * 18 + gt * 2 + 0] = 0.5f;
        out[(size_t)N_TOK * 18 + gt * 2 + 1] = 0.5f;
    }
}

__global__ void aux_kernel(float* __restrict__ out) {
    __shared__ float sq[NEXP];
    const int e = threadIdx.x;
    float s = 0.0f;
    for (int b = 0; b < NBLK; b++) s += g_partial[b * NEXP + e];
    const float m = s / (float)N_TOK;
    sq[e] = m * m;
    __syncthreads();
    if (e == 0) {
        float tot = 0.0f;
        for (int i = 0; i < NEXP; i++) tot += sq[i];
        out[(size_t)N_TOK * 20] = 0.01f * (tot / (float)NEXP);
    }
}

extern "C" void kernel_launch(void* const* d_in, const int* in_sizes, int n_in,
                              void* d_out, int out_size) {
    const float* x    = (const float*)d_in[0];
    const float* W    = (const float*)d_in[1];
    const float* bias = (const float*)d_in[2];
    float* out = (float*)d_out;

    cudaFuncSetAttribute(moe_main, cudaFuncAttributeMaxDynamicSharedMemorySize,
                         SMEM_BYTES);
    wconv_kernel<<<512, 256>>>(W);                  // 131072 quads
    moe_main<<<NBLK, NTHR, SMEM_BYTES>>>(x, bias, out);
    aux_kernel<<<1, NEXP>>>(out);
}

// round 7
// speedup vs baseline: 2.5999x; 1.6071x over previous
#include <cuda_runtime.h>
#include <cuda_pipeline.h>
#include <math.h>

#define N_TOK  16384
#define DIM    4096
#define NEXP   64
#define TOPK   8
#define TPB    128               // tokens per CTA
#define NTHR   256               // 8 warps
#define KC     64                // k per chunk
#define KSTEPS (KC / 16)         // 4 (k16 MMA steps)
#define NCHUNK (DIM / KC)        // 64
#define NBLK   (N_TOK / TPB)     // 128
#define PAD    72                // x row stride in floats (conflict-free for frag loads)

typedef unsigned int u32;

// Packed W fp16 fragment quads: [chunk][ks][n][t] -> {b0_hi, b1_hi, b0_lo*2048, b1_lo*2048}
__device__ __align__(16) uint4 g_Wq[NCHUNK * KSTEPS * NEXP * 4];   // 65536 quads, 1 MB
__device__ float g_partial[NBLK * NEXP];

// ---- smem byte offsets ----
#define XS(b)  ((b) * 36864)                    // 128 x 72 floats
#define WQ(b)  (73728 + (b) * 16384)            // 1024 uint4
#define SMEM_BYTES 106496
#define PROBS  0                                 // phase-2 alias: float[128][66]
#define BIAS_S 33792                             // float[64]

// split (x0, x1) -> hi fp16x2 (low half = x0), lo fp16x2 = ((x - hi) * 2048)
static __device__ __forceinline__ void split2(float x0, float x1, u32& h, u32& l) {
    asm("{\n\t"
        ".reg .b16 h0, h1;\n\t"
        ".reg .f32 u0, u1, r0, r1;\n\t"
        "cvt.rn.f16.f32 h0, %2;\n\t"
        "cvt.rn.f16.f32 h1, %3;\n\t"
        "mov.b32 %0, {h0, h1};\n\t"
        "cvt.f32.f16 u0, h0;\n\t"
        "cvt.f32.f16 u1, h1;\n\t"
        "sub.f32 r0, %2, u0;\n\t"
        "sub.f32 r1, %3, u1;\n\t"
        "mul.f32 r0, r0, 0f45000000;\n\t"
        "mul.f32 r1, r1, 0f45000000;\n\t"
        "cvt.rn.f16x2.f32 %1, r1, r0;\n\t"
        "}" : "=r"(h), "=r"(l) : "f"(x0), "f"(x1));
}

static __device__ __forceinline__ void mma_f16(float* c, u32 a0, u32 a1, u32 a2,
                                               u32 a3, u32 b0, u32 b1) {
    asm volatile(
        "mma.sync.aligned.m16n8k16.row.col.f32.f16.f16.f32 "
        "{%0,%1,%2,%3}, {%4,%5,%6,%7}, {%8,%9}, {%0,%1,%2,%3};"
        : "+f"(c[0]), "+f"(c[1]), "+f"(c[2]), "+f"(c[3])
        : "r"(a0), "r"(a1), "r"(a2), "r"(a3), "r"(b0), "r"(b1));
}
static __device__ __forceinline__ void mma_f16_z(float* d, u32 a0, u32 a1, u32 a2,
                                                 u32 a3, u32 b0, u32 b1) {
    asm volatile(
        "mma.sync.aligned.m16n8k16.row.col.f32.f16.f16.f32 "
        "{%0,%1,%2,%3}, {%4,%5,%6,%7}, {%8,%9}, {%10,%10,%10,%10};"
        : "=f"(d[0]), "=f"(d[1]), "=f"(d[2]), "=f"(d[3])
        : "r"(a0), "r"(a1), "r"(a2), "r"(a3), "r"(b0), "r"(b1), "f"(0.0f));
}

// ---- W pre-pack: fp32 -> fp16 split fragment quads ----
extern "C" __global__ void wconv_kernel(const float* __restrict__ W) {
    const int idx = blockIdx.x * blockDim.x + threadIdx.x;   // 65536 quads
    const int t  = idx & 3;
    const int n  = (idx >> 2) & 63;
    const int ks = (idx >> 8) & 3;
    const int c  = idx >> 10;
    const int k0 = c * KC + ks * 16;
    const float* wr = W + (size_t)n * DIM + k0;
    uint4 q;
    split2(wr[2 * t],     wr[2 * t + 1], q.x, q.z);   // b0: k = 2t, 2t+1
    split2(wr[2 * t + 8], wr[2 * t + 9], q.y, q.w);   // b1: k = 2t+8, 2t+9
    g_Wq[idx] = q;
}

extern "C" __global__ void __launch_bounds__(NTHR, 1)
moe_main(const float* __restrict__ x, const float* __restrict__ bias,
         float* __restrict__ out) {
    extern __shared__ char sm[];
    const int tid  = threadIdx.x;
    const int wid  = tid >> 5;
    const int lane = tid & 31;
    const int g    = lane >> 2;          // groupID 0..7
    const int t    = lane & 3;           // threadID in group 0..3
    const int tok0 = blockIdx.x * TPB;
    const int warpM = wid * 16;          // each warp owns one m16 tile

    // ---- cp.async stagers (256 threads) ----
    auto issue_chunk = [&](int c) {
        const int b  = c & 1;
        const int kc = c * KC;
        // x: 2048 float4 -> 8 per thread
#pragma unroll
        for (int i = 0; i < 8; i++) {
            const int flat = tid + (i << 8);
            const int row = flat >> 4;
            const int j   = flat & 15;
            __pipeline_memcpy_async(sm + XS(b) + row * (PAD * 4) + j * 16,
                                    x + (size_t)(tok0 + row) * DIM + kc + 4 * j, 16);
        }
        // W quads: 1024 uint4 -> 4 per thread
        const uint4* src = g_Wq + (size_t)c * (KSTEPS * NEXP * 4);
#pragma unroll
        for (int i = 0; i < 4; i++) {
            const int flat = tid + (i << 8);
            __pipeline_memcpy_async(sm + WQ(b) + flat * 16, src + flat, 16);
        }
    };

    // ---- accumulators: [ntile j][4] ----
    float accM[8][4];    // master fp32 (RN adds)
    float hh[8][4];      // per-chunk hi*hi (reset each chunk via mma_f16_z)
    float accx[8][4];    // cross terms, carries x2048 scale
#pragma unroll
    for (int j = 0; j < 8; j++)
#pragma unroll
        for (int q = 0; q < 4; q++) { accM[j][q] = 0.f; accx[j][q] = 0.f; }

    issue_chunk(0);
    __pipeline_commit();

#pragma unroll 1
    for (int c = 0; c < NCHUNK; c++) {
        const int b = c & 1;
        if (c + 1 < NCHUNK) issue_chunk(c + 1);
        __pipeline_commit();
        __pipeline_wait_prior((c + 1 < NCHUNK) ? 1 : 0);
        __syncthreads();

        const float* xs = reinterpret_cast<const float*>(sm + XS(b));
        const uint4* wq = reinterpret_cast<const uint4*>(sm + WQ(b));

#pragma unroll
        for (int ks = 0; ks < KSTEPS; ks++) {
            const int k0 = ks * 16;
            const int r0 = warpM + g;
            // A fragments for m16n8k16: 4 float2 loads, split to fp16 hi/lo
            const float2 v0 = *reinterpret_cast<const float2*>(xs + r0 * PAD + k0 + 2 * t);
            const float2 v1 = *reinterpret_cast<const float2*>(xs + (r0 + 8) * PAD + k0 + 2 * t);
            const float2 v2 = *reinterpret_cast<const float2*>(xs + r0 * PAD + k0 + 2 * t + 8);
            const float2 v3 = *reinterpret_cast<const float2*>(xs + (r0 + 8) * PAD + k0 + 2 * t + 8);
            u32 ah0, ah1, ah2, ah3, al0, al1, al2, al3;
            split2(v0.x, v0.y, ah0, al0);
            split2(v1.x, v1.y, ah1, al1);
            split2(v2.x, v2.y, ah2, al2);
            split2(v3.x, v3.y, ah3, al3);

            const uint4* wrow = wq + (ks * NEXP + g) * 4 + t;
#pragma unroll
            for (int j = 0; j < 8; j++) {
                const uint4 q = wrow[j * 32];   // n-tile 8j+g
                if (ks == 0) mma_f16_z(hh[j], ah0, ah1, ah2, ah3, q.x, q.y);
                else         mma_f16(hh[j], ah0, ah1, ah2, ah3, q.x, q.y);
                mma_f16(accx[j], ah0, ah1, ah2, ah3, q.z, q.w);   // hi * lo(scaled)
                mma_f16(accx[j], al0, al1, al2, al3, q.x, q.y);   // lo(scaled) * hi
            }
        }
        // fold chunk hi*hi into master with RN adds (breaks truncation chaining)
#pragma unroll
        for (int j = 0; j < 8; j++)
#pragma unroll
            for (int q = 0; q < 4; q++) accM[j][q] += hh[j][q];
        __syncthreads();
    }

    // ---- epilogue: logits = accM + accx / 2048 ----
    float* ps = reinterpret_cast<float*>(sm + PROBS);   // [128][66]
    {
        const int r0 = warpM + g;
        const float s = 4.8828125e-4f;   // 1/2048
#pragma unroll
        for (int j = 0; j < 8; j++) {
            const int col = 8 * j + 2 * t;
            const float f0 = fmaf(accx[j][0], s, accM[j][0]);
            const float f1 = fmaf(accx[j][1], s, accM[j][1]);
            const float f2 = fmaf(accx[j][2], s, accM[j][2]);
            const float f3 = fmaf(accx[j][3], s, accM[j][3]);
            *reinterpret_cast<float2*>(ps + r0 * 66 + col)       = make_float2(f0, f1);
            *reinterpret_cast<float2*>(ps + (r0 + 8) * 66 + col) = make_float2(f2, f3);
        }
    }
    if (tid < NEXP) reinterpret_cast<float*>(sm + BIAS_S)[tid] = bias[tid];
    __syncthreads();

    // ---- phase 2: softmax + top-8 (threads 0..127, thread == token) ----
    const int tok = tid;
    float lv[NEXP];
    if (tok < TPB) {
        const float* bs = reinterpret_cast<const float*>(sm + BIAS_S);
        float mx = -INFINITY;
#pragma unroll
        for (int e = 0; e < NEXP; e++) {
            const float v = ps[tok * 66 + e] + bs[e];
            lv[e] = v;
            mx = fmaxf(mx, v);
        }
        float ssum = 0.0f;
#pragma unroll
        for (int e = 0; e < NEXP; e++) {
            lv[e] = expf(lv[e] - mx);
            ssum += lv[e];
        }
        const float inv = 1.0f / ssum;
#pragma unroll
        for (int e = 0; e < NEXP; e++) lv[e] *= inv;
    }
    __syncthreads();
    if (tok < TPB) {
#pragma unroll
        for (int e = 0; e < NEXP; e++) ps[tok * 66 + e] = lv[e];
    }
    __syncthreads();

    if (tid < NEXP) {
        float cs = 0.0f;
        for (int tt = 0; tt < TPB; tt++) cs += ps[tt * 66 + tid];
        g_partial[blockIdx.x * NEXP + tid] = cs;
    }

    if (tok < TPB) {
        const int gt = tok0 + tok;
        float prevV = INFINITY;
        int   prevE = -1;
        float* o_ids = out;
        float* o_p   = out + (size_t)N_TOK * 8;
#pragma unroll
        for (int r = 0; r < TOPK; r++) {
            float bv = -INFINITY;
            int   be = 0;
#pragma unroll
            for (int e = 0; e < NEXP; e++) {
                const float v = lv[e];
                const bool elig = (v < prevV) || (v == prevV && e > prevE);
                if (elig && v > bv) { bv = v; be = e; }
            }
            o_ids[(size_t)gt * 8 + r] = (float)be;
            o_p[(size_t)gt * 8 + r]   = bv;
            prevV = bv; prevE = be;
        }
        out[(size_t)N_TOK * 16 + gt * 2 + 0] = 0.0f;
        out[(size_t)N_TOK * 16 + gt * 2 + 1] = 1.0f;
        out[(size_t)N_TOK * 18 + gt * 2 + 0] = 0.5f;
        out[(size_t)N_TOK * 18 + gt * 2 + 1] = 0.5f;
    }
}

__global__ void aux_kernel(float* __restrict__ out) {
    __shared__ float sq[NEXP];
    const int e = threadIdx.x;
    float s = 0.0f;
    for (int b = 0; b < NBLK; b++) s += g_partial[b * NEXP + e];
    const float m = s / (float)N_TOK;
    sq[e] = m * m;
    __syncthreads();
    if (e == 0) {
        float tot = 0.0f;
        for (int i = 0; i < NEXP; i++) tot += sq[i];
        out[(size_t)N_TOK * 20] = 0.01f * (tot / (float)NEXP);
    }
}

extern "C" void kernel_launch(void* const* d_in, const int* in_sizes, int n_in,
                              void* d_out, int out_size) {
    const float* x    = (const float*)d_in[0];
    const float* W    = (const float*)d_in[1];
    const float* bias = (const float*)d_in[2];
    float* out = (float*)d_out;

    cudaFuncSetAttribute(moe_main, cudaFuncAttributeMaxDynamicSharedMemorySize,
                         SMEM_BYTES);
    wconv_kernel<<<256, 256>>>(W);                  // 65536 quads
    moe_main<<<NBLK, NTHR, SMEM_BYTES>>>(x, bias, out);
    aux_kernel<<<1, NEXP>>>(out);
}